// round 16
// baseline (speedup 1.0000x reference)
#include <cuda_runtime.h>
#include <cuda_bf16.h>
#include <cstdint>

#define BATCH   65536
#define D0      768
#define D1      512
#define D2      256
#define D3      128
#define NCODES  256
#define NLEVELS 4
#define BETA_F  0.25f
#define QBLOCKS 256

typedef unsigned long long ull;
typedef __nv_bfloat16 bf16;

// ---------------- scratch (no cudaMalloc allowed) ----------------
__device__ float g_h1[(size_t)BATCH * D1];     // 128 MB
__device__ float g_h2[(size_t)BATCH * D2];     //  64 MB
__device__ float g_z [(size_t)BATCH * D3];     //  32 MB
__device__ uint32_t g_idx[BATCH];              // packed codebook indices
__device__ float g_P[NLEVELS * NCODES * D2];   // 1 MB: P = codebooks @ dw0
__device__ float g_zb[D2];                     // zero bias (zero-initialized)
__device__ float g_loss_part[QBLOCKS];
// bf16 2-way split decoder weights (dw1, dw2), [N][K]
#define WTD_TOTAL 524288
__device__ bf16 g_wb0[WTD_TOTAL];
__device__ bf16 g_wb1[WTD_TOTAL];

// ---------------- helpers ----------------
__device__ __forceinline__ void split2(float v, bf16& h, bf16& m) {
    h = __float2bfloat16_rn(v);
    m = __float2bfloat16_rn(v - __bfloat162float(h));
}
__device__ __forceinline__ void mma_bf16(float* c, const uint32_t* a,
                                         const uint32_t* b) {
    asm volatile(
        "mma.sync.aligned.m16n8k16.row.col.f32.bf16.bf16.f32 "
        "{%0,%1,%2,%3}, {%4,%5,%6,%7}, {%8,%9}, {%0,%1,%2,%3};"
        : "+f"(c[0]), "+f"(c[1]), "+f"(c[2]), "+f"(c[3])
        : "r"(a[0]), "r"(a[1]), "r"(a[2]), "r"(a[3]), "r"(b[0]), "r"(b[1]));
}

#define PACK2(d, lo, hi) \
    asm("mov.b64 %0, {%1, %2};" : "=l"(d) : "f"(lo), "f"(hi))
#define UNPACK2(lo, hi, v) \
    asm("mov.b64 {%0, %1}, %2;" : "=f"(lo), "=f"(hi) : "l"(v))
#define FMA2(d, a, b) \
    asm("fma.rn.f32x2 %0, %1, %2, %0;" : "+l"(d) : "l"(a), "l"(b))
#define FMA2D(d, a, b, c) \
    asm("fma.rn.f32x2 %0, %1, %2, %3;" : "=l"(d) : "l"(a), "l"(b), "l"(c))

// ------ decoder weight split + transpose: W[K,N] fp32 -> 2x bf16 [N,K] ------
__global__ void wsplit(const float* __restrict__ W, bf16* __restrict__ B0,
                       bf16* __restrict__ B1, int K, int N)
{
    int id = blockIdx.x * 256 + threadIdx.x;
    if (id >= K * N) return;
    int n = id / K, k = id % K;
    bf16 h, m;
    split2(W[(size_t)k * N + n], h, m);
    B0[id] = h; B1[id] = m;
}

// ---------------- scalar fp32 GEMM (R6 proven, no hints) -------------------
template <bool RELU>
__global__ __launch_bounds__(256) void sgemm_bias(
    const float* __restrict__ A, const float* __restrict__ W,
    const float* __restrict__ bias, float* __restrict__ C,
    int M, int N, int K)
{
    constexpr int BK = 16;
    __shared__ __align__(16) float As[BK][128];
    __shared__ __align__(16) float Bs[BK][64];

    const int tid = threadIdx.x;
    const int tx  = tid & 15;
    const int ty  = tid >> 4;
    const int rowBase = blockIdx.y * 128;
    const int colBase = blockIdx.x * 64;

    float acc[8][4];
#pragma unroll
    for (int i = 0; i < 8; i++)
#pragma unroll
        for (int j = 0; j < 4; j++) acc[i][j] = 0.0f;

    for (int k0 = 0; k0 < K; k0 += BK) {
#pragma unroll
        for (int t = 0; t < 2; t++) {
            int f  = tid + t * 256;
            int ar = f >> 2, aq = f & 3;
            float4 v = *reinterpret_cast<const float4*>(
                &A[(size_t)(rowBase + ar) * K + k0 + aq * 4]);
            As[aq * 4 + 0][ar] = v.x;
            As[aq * 4 + 1][ar] = v.y;
            As[aq * 4 + 2][ar] = v.z;
            As[aq * 4 + 3][ar] = v.w;
        }
        {
            int br = tid >> 4, bc = tid & 15;
            float4 v = *reinterpret_cast<const float4*>(
                &W[(size_t)(k0 + br) * N + colBase + bc * 4]);
            *reinterpret_cast<float4*>(&Bs[br][bc * 4]) = v;
        }
        __syncthreads();

#pragma unroll
        for (int kk = 0; kk < BK; kk++) {
            float4 a0 = *reinterpret_cast<const float4*>(&As[kk][ty * 8]);
            float4 a1 = *reinterpret_cast<const float4*>(&As[kk][ty * 8 + 4]);
            float4 b  = *reinterpret_cast<const float4*>(&Bs[kk][tx * 4]);
            float a[8] = {a0.x, a0.y, a0.z, a0.w, a1.x, a1.y, a1.z, a1.w};
#pragma unroll
            for (int i = 0; i < 8; i++) {
                acc[i][0] += a[i] * b.x;
                acc[i][1] += a[i] * b.y;
                acc[i][2] += a[i] * b.z;
                acc[i][3] += a[i] * b.w;
            }
        }
        __syncthreads();
    }

    float4 bv = *reinterpret_cast<const float4*>(&bias[colBase + tx * 4]);
#pragma unroll
    for (int i = 0; i < 8; i++) {
        int r = rowBase + ty * 8 + i;
        float4 o;
        o.x = acc[i][0] + bv.x;
        o.y = acc[i][1] + bv.y;
        o.z = acc[i][2] + bv.z;
        o.w = acc[i][3] + bv.w;
        if (RELU) {
            o.x = fmaxf(o.x, 0.0f); o.y = fmaxf(o.y, 0.0f);
            o.z = fmaxf(o.z, 0.0f); o.w = fmaxf(o.w, 0.0f);
        }
        *reinterpret_cast<float4*>(&C[(size_t)r * N + colBase + tx * 4]) = o;
    }
}

// -------- decoder GEMM: mma.sync bf16x2 (R6 proven, verbatim) --------------
template <bool RELU>
__global__ __launch_bounds__(256) void mma_gemm(
    const float* __restrict__ A, const bf16* __restrict__ W0,
    const bf16* __restrict__ W1, const float* __restrict__ bias,
    float* __restrict__ C, int M, int N, int K)
{
    __shared__ bf16 As0[128 * 16], As1[128 * 16];
    __shared__ bf16 Bs0[128 * 16], Bs1[128 * 16];

    const int tid  = threadIdx.x;
    const int wid  = tid >> 5;
    const int lane = tid & 31;
    const int g    = lane >> 2;
    const int t    = lane & 3;
    const int mWarp = (wid & 3) * 32;
    const int nWarp = (wid >> 2) * 64;
    const int rowBase = blockIdx.y * 128;
    const int colBase = blockIdx.x * 128;

    float acc[2][8][4];
#pragma unroll
    for (int i = 0; i < 2; i++)
#pragma unroll
        for (int j = 0; j < 8; j++)
#pragma unroll
            for (int q = 0; q < 4; q++) acc[i][j][q] = 0.0f;

    float4 stA[2];
    uint4  stB0, stB1;

    auto ldchunk = [&](int k0) {
#pragma unroll
        for (int tt = 0; tt < 2; tt++) {
            int idx = tid + tt * 256;
            int m = idx >> 2, q = idx & 3;
            stA[tt] = *reinterpret_cast<const float4*>(
                &A[(size_t)(rowBase + m) * K + k0 + q * 4]);
        }
        {
            int n = tid >> 1, kq = tid & 1;
            size_t gi = (size_t)(colBase + n) * K + k0 + kq * 8;
            stB0 = *reinterpret_cast<const uint4*>(&W0[gi]);
            stB1 = *reinterpret_cast<const uint4*>(&W1[gi]);
        }
    };
    auto stchunk = [&]() {
#pragma unroll
        for (int tt = 0; tt < 2; tt++) {
            int idx = tid + tt * 256;
            int m = idx >> 2, q = idx & 3;
            const float* vv = &stA[tt].x;
            bf16 h[4], mm[4];
#pragma unroll
            for (int j = 0; j < 4; j++) split2(vv[j], h[j], mm[j]);
            int o = m * 16 + q * 4;
            *reinterpret_cast<__nv_bfloat162*>(&As0[o])     = {h[0],  h[1]};
            *reinterpret_cast<__nv_bfloat162*>(&As0[o + 2]) = {h[2],  h[3]};
            *reinterpret_cast<__nv_bfloat162*>(&As1[o])     = {mm[0], mm[1]};
            *reinterpret_cast<__nv_bfloat162*>(&As1[o + 2]) = {mm[2], mm[3]};
        }
        {
            int n = tid >> 1, kq = tid & 1;
            int o = n * 16 + kq * 8;
            *reinterpret_cast<uint4*>(&Bs0[o]) = stB0;
            *reinterpret_cast<uint4*>(&Bs1[o]) = stB1;
        }
    };

    ldchunk(0);
    for (int k0 = 0; k0 < K; k0 += 16) {
        stchunk();
        __syncthreads();
        if (k0 + 16 < K) ldchunk(k0 + 16);

        uint32_t aF[2][2][4];
#pragma unroll
        for (int ma = 0; ma < 2; ma++) {
            int m0 = mWarp + ma * 16 + g;
            int b0 = m0 * 16 + 2 * t;
#pragma unroll
            for (int s = 0; s < 2; s++) {
                const bf16* As = (s == 0) ? As0 : As1;
                aF[s][ma][0] = *reinterpret_cast<const uint32_t*>(&As[b0]);
                aF[s][ma][1] = *reinterpret_cast<const uint32_t*>(&As[b0 + 8 * 16]);
                aF[s][ma][2] = *reinterpret_cast<const uint32_t*>(&As[b0 + 8]);
                aF[s][ma][3] = *reinterpret_cast<const uint32_t*>(&As[b0 + 8 * 16 + 8]);
            }
        }
#pragma unroll
        for (int nb = 0; nb < 8; nb++) {
            int n = nWarp + nb * 8 + g;
            int b0 = n * 16 + 2 * t;
            uint32_t bF[2][2];
#pragma unroll
            for (int s = 0; s < 2; s++) {
                const bf16* Bsx = (s == 0) ? Bs0 : Bs1;
                bF[s][0] = *reinterpret_cast<const uint32_t*>(&Bsx[b0]);
                bF[s][1] = *reinterpret_cast<const uint32_t*>(&Bsx[b0 + 8]);
            }
#pragma unroll
            for (int ma = 0; ma < 2; ma++) {
                float* c = acc[ma][nb];
                mma_bf16(c, aF[0][ma], bF[1]);   // h*m
                mma_bf16(c, aF[1][ma], bF[0]);   // m*h
                mma_bf16(c, aF[0][ma], bF[0]);   // h*h
            }
        }
        __syncthreads();
    }

#pragma unroll
    for (int ma = 0; ma < 2; ma++) {
        int row0 = rowBase + mWarp + ma * 16 + g;
#pragma unroll
        for (int nb = 0; nb < 8; nb++) {
            int col = colBase + nWarp + nb * 8 + 2 * t;
            float2 bv = *reinterpret_cast<const float2*>(&bias[col]);
            float2 v0, v1;
            v0.x = acc[ma][nb][0] + bv.x;
            v0.y = acc[ma][nb][1] + bv.y;
            v1.x = acc[ma][nb][2] + bv.x;
            v1.y = acc[ma][nb][3] + bv.y;
            if (RELU) {
                v0.x = fmaxf(v0.x, 0.f); v0.y = fmaxf(v0.y, 0.f);
                v1.x = fmaxf(v1.x, 0.f); v1.y = fmaxf(v1.y, 0.f);
            }
            *reinterpret_cast<float2*>(&C[(size_t)row0 * N + col]) = v0;
            *reinterpret_cast<float2*>(&C[(size_t)(row0 + 8) * N + col]) = v1;
        }
    }
}

// ---------------- fused residual quantization -> packed indices ------------
__global__ __launch_bounds__(256) void quant_all(
    const float* __restrict__ z, const float* __restrict__ codebooks,
    uint32_t* __restrict__ idxOut, float* __restrict__ partials)
{
    __shared__ __align__(16) float sC[64 * D3];
    __shared__ float snorm[64];
    __shared__ float sred[256];

    const int tid = threadIdx.x;
    const size_t row = (size_t)blockIdx.x * 256 + tid;

    ull r2[64];
    {
        const ulonglong2* zp = reinterpret_cast<const ulonglong2*>(z + row * D3);
#pragma unroll
        for (int k = 0; k < 32; k++) {
            ulonglong2 v = zp[k];
            r2[2 * k] = v.x; r2[2 * k + 1] = v.y;
        }
    }
    ull mone; PACK2(mone, -1.0f, -1.0f);
    ull ls0 = 0ULL, ls1 = 0ULL;
    uint32_t packed = 0;

    for (int l = 0; l < NLEVELS; l++) {
        const float* C = codebooks + (size_t)l * NCODES * D3;
        float best = 3.4e38f;
        int bi = 0;

        for (int ch = 0; ch < 4; ch++) {
            __syncthreads();
            const float4* src =
                reinterpret_cast<const float4*>(C + (size_t)ch * 64 * D3);
            float4* dst = reinterpret_cast<float4*>(sC);
#pragma unroll
            for (int i = 0; i < 8; i++) dst[tid + i * 256] = src[tid + i * 256];
            __syncthreads();
            if (tid < 64) {
                const float4* cp = reinterpret_cast<const float4*>(sC + tid * D3);
                float s = 0.0f;
#pragma unroll
                for (int i = 0; i < 32; i++) {
                    float4 v = cp[i];
                    s += v.x * v.x + v.y * v.y + v.z * v.z + v.w * v.w;
                }
                snorm[tid] = s;
            }
            __syncthreads();

            for (int c = 0; c < 64; c++) {
                const ulonglong2* cp =
                    reinterpret_cast<const ulonglong2*>(sC + c * D3);
                ull a0 = 0ULL, a1 = 0ULL;
#pragma unroll
                for (int k = 0; k < 32; k++) {
                    ulonglong2 v = cp[k];
                    FMA2(a0, r2[2 * k],     v.x);
                    FMA2(a1, r2[2 * k + 1], v.y);
                }
                float s0, s1, s2, s3;
                UNPACK2(s0, s1, a0);
                UNPACK2(s2, s3, a1);
                float dot = (s0 + s1) + (s2 + s3);
                float score = snorm[c] - 2.0f * dot;
                if (score < best) { best = score; bi = ch * 64 + c; }
            }
        }

        packed |= (uint32_t)bi << (8 * l);

        const ulonglong2* qp =
            reinterpret_cast<const ulonglong2*>(C + (size_t)bi * D3);
#pragma unroll
        for (int k = 0; k < 32; k++) {
            ulonglong2 q = qp[k];
            ull d0, d1;
            FMA2D(d0, q.x, mone, r2[2 * k]);      // r - q
            FMA2D(d1, q.y, mone, r2[2 * k + 1]);
            FMA2(ls0, d0, d0);
            FMA2(ls1, d1, d1);
            r2[2 * k] = d0; r2[2 * k + 1] = d1;
        }
    }

    idxOut[row] = packed;

    float s0, s1, s2, s3;
    UNPACK2(s0, s1, ls0);
    UNPACK2(s2, s3, ls1);
    sred[tid] = (s0 + s1) + (s2 + s3);
    __syncthreads();
#pragma unroll
    for (int s = 128; s > 0; s >>= 1) {
        if (tid < s) sred[tid] += sred[tid + s];
        __syncthreads();
    }
    if (tid == 0) partials[blockIdx.x] = sred[0];
}

// ---------------- dec1 via lookup: h2 = relu(Σ_l P[l][idx_l] + db0) --------
__global__ __launch_bounds__(256) void dec1_lookup(
    const uint32_t* __restrict__ idx, const float* __restrict__ P,
    const float* __restrict__ bias, float* __restrict__ h2)
{
    const int tid = threadIdx.x;
    const int row = blockIdx.x * 32 + (tid >> 3);
    const int c0  = (tid & 7) * 32;

    uint32_t iw = idx[row];
    float4 acc[8];
    const float4* bp = reinterpret_cast<const float4*>(bias + c0);
#pragma unroll
    for (int j = 0; j < 8; j++) acc[j] = bp[j];

#pragma unroll
    for (int l = 0; l < NLEVELS; l++) {
        int code = (iw >> (8 * l)) & 255;
        const float4* pp = reinterpret_cast<const float4*>(
            P + ((size_t)(l * NCODES + code) * D2) + c0);
#pragma unroll
        for (int j = 0; j < 8; j++) {
            float4 v = pp[j];
            acc[j].x += v.x; acc[j].y += v.y;
            acc[j].z += v.z; acc[j].w += v.w;
        }
    }

    float4* op = reinterpret_cast<float4*>(h2 + (size_t)row * D2 + c0);
#pragma unroll
    for (int j = 0; j < 8; j++) {
        float4 o = acc[j];
        o.x = fmaxf(o.x, 0.f); o.y = fmaxf(o.y, 0.f);
        o.z = fmaxf(o.z, 0.f); o.w = fmaxf(o.w, 0.f);
        op[j] = o;
    }
}

// ---------------- deterministic loss finalize ----------------
__global__ void finalize_loss(const float* __restrict__ partials,
                              float* __restrict__ out)
{
    if (threadIdx.x == 0 && blockIdx.x == 0) {
        float tot = 0.0f;
        for (int i = 0; i < QBLOCKS; i++) tot += partials[i];
        float rq = (1.0f + BETA_F) * tot /
                   ((float)NLEVELS * (float)BATCH * (float)D3);
        *out = rq;
    }
}

// ---------------- launch ----------------
extern "C" void kernel_launch(void* const* d_in, const int* in_sizes, int n_in,
                              void* d_out, int out_size)
{
    (void)in_sizes; (void)n_in;
    const float* x   = (const float*)d_in[0];
    const float* ew0 = (const float*)d_in[1];
    const float* eb0 = (const float*)d_in[2];
    const float* ew1 = (const float*)d_in[3];
    const float* eb1 = (const float*)d_in[4];
    const float* ew2 = (const float*)d_in[5];
    const float* eb2 = (const float*)d_in[6];
    const float* dw0 = (const float*)d_in[7];
    const float* db0 = (const float*)d_in[8];
    const float* dw1 = (const float*)d_in[9];
    const float* db1 = (const float*)d_in[10];
    const float* dw2 = (const float*)d_in[11];
    const float* db2 = (const float*)d_in[12];
    const float* cb  = (const float*)d_in[13];
    float* out = (float*)d_out;

    float *h1, *h2, *z, *P, *zb, *lp;
    uint32_t* idx;
    bf16 *w0, *w1;
    cudaGetSymbolAddress((void**)&h1,  g_h1);
    cudaGetSymbolAddress((void**)&h2,  g_h2);
    cudaGetSymbolAddress((void**)&z,   g_z);
    cudaGetSymbolAddress((void**)&idx, g_idx);
    cudaGetSymbolAddress((void**)&P,   g_P);
    cudaGetSymbolAddress((void**)&zb,  g_zb);
    cudaGetSymbolAddress((void**)&lp,  g_loss_part);
    cudaGetSymbolAddress((void**)&w0,  g_wb0);
    cudaGetSymbolAddress((void**)&w1,  g_wb1);

    // decoder weight splits for dw1, dw2 only (transposed to [N][K])
    // dw1: 256x512 -> offset 0 ; dw2: 512x768 -> offset 131072
    wsplit<<<(D2 * D1 + 255) / 256, 256>>>(dw1, w0,          w1,          D2, D1);
    wsplit<<<(D1 * D0 + 255) / 256, 256>>>(dw2, w0 + 131072, w1 + 131072, D1, D0);

    const int MB = BATCH / 128;

    // P = codebooks @ dw0  (M=1024, N=256, K=128)
    sgemm_bias<false><<<dim3(D2 / 64, (NLEVELS * NCODES) / 128), 256>>>(
        cb, dw0, zb, P, NLEVELS * NCODES, D2, D3);

    // encoder: scalar (flip-safe)
    sgemm_bias<true ><<<dim3(D1 / 64, MB), 256>>>(x,  ew0, eb0, h1, BATCH, D1, D0);
    sgemm_bias<true ><<<dim3(D2 / 64, MB), 256>>>(h1, ew1, eb1, h2, BATCH, D2, D1);
    sgemm_bias<false><<<dim3(D3 / 64, MB), 256>>>(h2, ew2, eb2, z,  BATCH, D3, D2);

    // fused residual quantization -> indices + loss partials
    quant_all<<<QBLOCKS, 256>>>(z, cb, idx, lp);

    // dec1 via table lookup
    dec1_lookup<<<BATCH / 32, 256>>>(idx, P, db0, h2);

    // dec2, dec3: bf16x2 mma (R6 proven decoder)
    mma_gemm<true ><<<dim3(D1 / 128, MB), 256>>>(h2, w0,          w1,          db1, h1,  BATCH, D1, D2);
    mma_gemm<false><<<dim3(D0 / 128, MB), 256>>>(h1, w0 + 131072, w1 + 131072, db2, out, BATCH, D0, D1);

    finalize_loss<<<1, 32>>>(lp, out + (size_t)out_size - 1);
}

// round 17
// speedup vs baseline: 1.0003x; 1.0003x over previous
#include <cuda_runtime.h>
#include <cuda_bf16.h>
#include <cstdint>

#define BATCH   65536
#define D0      768
#define D1      512
#define D2      256
#define D3      128
#define NCODES  256
#define NLEVELS 4
#define BETA_F  0.25f
#define QBLOCKS 256

typedef unsigned long long ull;
typedef __nv_bfloat16 bf16;

// ---------------- scratch (no cudaMalloc allowed) ----------------
__device__ float g_h1[(size_t)BATCH * D1];     // 128 MB
__device__ float g_h2[(size_t)BATCH * D2];     //  64 MB
__device__ float g_z [(size_t)BATCH * D3];     //  32 MB
__device__ uint32_t g_idx[BATCH];              // packed codebook indices
__device__ float g_P[NLEVELS * NCODES * D2];   // 1 MB: P = codebooks @ dw0
__device__ float g_zb[D2];                     // zero bias (zero-initialized)
__device__ float g_loss_part[QBLOCKS];
// bf16 2-way split decoder weights (dw1, dw2), [N][K]
#define WTD_TOTAL 524288
__device__ bf16 g_wb0[WTD_TOTAL];
__device__ bf16 g_wb1[WTD_TOTAL];

// ---------------- helpers ----------------
__device__ __forceinline__ void split2(float v, bf16& h, bf16& m) {
    h = __float2bfloat16_rn(v);
    m = __float2bfloat16_rn(v - __bfloat162float(h));
}
__device__ __forceinline__ void mma_bf16(float* c, const uint32_t* a,
                                         const uint32_t* b) {
    asm volatile(
        "mma.sync.aligned.m16n8k16.row.col.f32.bf16.bf16.f32 "
        "{%0,%1,%2,%3}, {%4,%5,%6,%7}, {%8,%9}, {%0,%1,%2,%3};"
        : "+f"(c[0]), "+f"(c[1]), "+f"(c[2]), "+f"(c[3])
        : "r"(a[0]), "r"(a[1]), "r"(a[2]), "r"(a[3]), "r"(b[0]), "r"(b[1]));
}

#define PACK2(d, lo, hi) \
    asm("mov.b64 %0, {%1, %2};" : "=l"(d) : "f"(lo), "f"(hi))
#define UNPACK2(lo, hi, v) \
    asm("mov.b64 {%0, %1}, %2;" : "=f"(lo), "=f"(hi) : "l"(v))
#define FMA2(d, a, b) \
    asm("fma.rn.f32x2 %0, %1, %2, %0;" : "+l"(d) : "l"(a), "l"(b))
#define FMA2D(d, a, b, c) \
    asm("fma.rn.f32x2 %0, %1, %2, %3;" : "=l"(d) : "l"(a), "l"(b), "l"(c))

// ------ decoder weight split + transpose: W[K,N] fp32 -> 2x bf16 [N,K] ------
__global__ void wsplit(const float* __restrict__ W, bf16* __restrict__ B0,
                       bf16* __restrict__ B1, int K, int N)
{
    int id = blockIdx.x * 256 + threadIdx.x;
    if (id >= K * N) return;
    int n = id / K, k = id % K;
    bf16 h, m;
    split2(W[(size_t)k * N + n], h, m);
    B0[id] = h; B1[id] = m;
}

// ---------------- scalar fp32 GEMM (R6 proven, no hints) -------------------
template <bool RELU>
__global__ __launch_bounds__(256) void sgemm_bias(
    const float* __restrict__ A, const float* __restrict__ W,
    const float* __restrict__ bias, float* __restrict__ C,
    int M, int N, int K)
{
    constexpr int BK = 16;
    __shared__ __align__(16) float As[BK][128];
    __shared__ __align__(16) float Bs[BK][64];

    const int tid = threadIdx.x;
    const int tx  = tid & 15;
    const int ty  = tid >> 4;
    const int rowBase = blockIdx.y * 128;
    const int colBase = blockIdx.x * 64;

    float acc[8][4];
#pragma unroll
    for (int i = 0; i < 8; i++)
#pragma unroll
        for (int j = 0; j < 4; j++) acc[i][j] = 0.0f;

    for (int k0 = 0; k0 < K; k0 += BK) {
#pragma unroll
        for (int t = 0; t < 2; t++) {
            int f  = tid + t * 256;
            int ar = f >> 2, aq = f & 3;
            float4 v = *reinterpret_cast<const float4*>(
                &A[(size_t)(rowBase + ar) * K + k0 + aq * 4]);
            As[aq * 4 + 0][ar] = v.x;
            As[aq * 4 + 1][ar] = v.y;
            As[aq * 4 + 2][ar] = v.z;
            As[aq * 4 + 3][ar] = v.w;
        }
        {
            int br = tid >> 4, bc = tid & 15;
            float4 v = *reinterpret_cast<const float4*>(
                &W[(size_t)(k0 + br) * N + colBase + bc * 4]);
            *reinterpret_cast<float4*>(&Bs[br][bc * 4]) = v;
        }
        __syncthreads();

#pragma unroll
        for (int kk = 0; kk < BK; kk++) {
            float4 a0 = *reinterpret_cast<const float4*>(&As[kk][ty * 8]);
            float4 a1 = *reinterpret_cast<const float4*>(&As[kk][ty * 8 + 4]);
            float4 b  = *reinterpret_cast<const float4*>(&Bs[kk][tx * 4]);
            float a[8] = {a0.x, a0.y, a0.z, a0.w, a1.x, a1.y, a1.z, a1.w};
#pragma unroll
            for (int i = 0; i < 8; i++) {
                acc[i][0] += a[i] * b.x;
                acc[i][1] += a[i] * b.y;
                acc[i][2] += a[i] * b.z;
                acc[i][3] += a[i] * b.w;
            }
        }
        __syncthreads();
    }

    float4 bv = *reinterpret_cast<const float4*>(&bias[colBase + tx * 4]);
#pragma unroll
    for (int i = 0; i < 8; i++) {
        int r = rowBase + ty * 8 + i;
        float4 o;
        o.x = acc[i][0] + bv.x;
        o.y = acc[i][1] + bv.y;
        o.z = acc[i][2] + bv.z;
        o.w = acc[i][3] + bv.w;
        if (RELU) {
            o.x = fmaxf(o.x, 0.0f); o.y = fmaxf(o.y, 0.0f);
            o.z = fmaxf(o.z, 0.0f); o.w = fmaxf(o.w, 0.0f);
        }
        *reinterpret_cast<float4*>(&C[(size_t)r * N + colBase + tx * 4]) = o;
    }
}

// -------- decoder GEMM: mma.sync bf16x2 (R6 proven, verbatim) --------------
template <bool RELU>
__global__ __launch_bounds__(256) void mma_gemm(
    const float* __restrict__ A, const bf16* __restrict__ W0,
    const bf16* __restrict__ W1, const float* __restrict__ bias,
    float* __restrict__ C, int M, int N, int K)
{
    __shared__ bf16 As0[128 * 16], As1[128 * 16];
    __shared__ bf16 Bs0[128 * 16], Bs1[128 * 16];

    const int tid  = threadIdx.x;
    const int wid  = tid >> 5;
    const int lane = tid & 31;
    const int g    = lane >> 2;
    const int t    = lane & 3;
    const int mWarp = (wid & 3) * 32;
    const int nWarp = (wid >> 2) * 64;
    const int rowBase = blockIdx.y * 128;
    const int colBase = blockIdx.x * 128;

    float acc[2][8][4];
#pragma unroll
    for (int i = 0; i < 2; i++)
#pragma unroll
        for (int j = 0; j < 8; j++)
#pragma unroll
            for (int q = 0; q < 4; q++) acc[i][j][q] = 0.0f;

    float4 stA[2];
    uint4  stB0, stB1;

    auto ldchunk = [&](int k0) {
#pragma unroll
        for (int tt = 0; tt < 2; tt++) {
            int idx = tid + tt * 256;
            int m = idx >> 2, q = idx & 3;
            stA[tt] = *reinterpret_cast<const float4*>(
                &A[(size_t)(rowBase + m) * K + k0 + q * 4]);
        }
        {
            int n = tid >> 1, kq = tid & 1;
            size_t gi = (size_t)(colBase + n) * K + k0 + kq * 8;
            stB0 = *reinterpret_cast<const uint4*>(&W0[gi]);
            stB1 = *reinterpret_cast<const uint4*>(&W1[gi]);
        }
    };
    auto stchunk = [&]() {
#pragma unroll
        for (int tt = 0; tt < 2; tt++) {
            int idx = tid + tt * 256;
            int m = idx >> 2, q = idx & 3;
            const float* vv = &stA[tt].x;
            bf16 h[4], mm[4];
#pragma unroll
            for (int j = 0; j < 4; j++) split2(vv[j], h[j], mm[j]);
            int o = m * 16 + q * 4;
            *reinterpret_cast<__nv_bfloat162*>(&As0[o])     = {h[0],  h[1]};
            *reinterpret_cast<__nv_bfloat162*>(&As0[o + 2]) = {h[2],  h[3]};
            *reinterpret_cast<__nv_bfloat162*>(&As1[o])     = {mm[0], mm[1]};
            *reinterpret_cast<__nv_bfloat162*>(&As1[o + 2]) = {mm[2], mm[3]};
        }
        {
            int n = tid >> 1, kq = tid & 1;
            int o = n * 16 + kq * 8;
            *reinterpret_cast<uint4*>(&Bs0[o]) = stB0;
            *reinterpret_cast<uint4*>(&Bs1[o]) = stB1;
        }
    };

    ldchunk(0);
    for (int k0 = 0; k0 < K; k0 += 16) {
        stchunk();
        __syncthreads();
        if (k0 + 16 < K) ldchunk(k0 + 16);

        uint32_t aF[2][2][4];
#pragma unroll
        for (int ma = 0; ma < 2; ma++) {
            int m0 = mWarp + ma * 16 + g;
            int b0 = m0 * 16 + 2 * t;
#pragma unroll
            for (int s = 0; s < 2; s++) {
                const bf16* As = (s == 0) ? As0 : As1;
                aF[s][ma][0] = *reinterpret_cast<const uint32_t*>(&As[b0]);
                aF[s][ma][1] = *reinterpret_cast<const uint32_t*>(&As[b0 + 8 * 16]);
                aF[s][ma][2] = *reinterpret_cast<const uint32_t*>(&As[b0 + 8]);
                aF[s][ma][3] = *reinterpret_cast<const uint32_t*>(&As[b0 + 8 * 16 + 8]);
            }
        }
#pragma unroll
        for (int nb = 0; nb < 8; nb++) {
            int n = nWarp + nb * 8 + g;
            int b0 = n * 16 + 2 * t;
            uint32_t bF[2][2];
#pragma unroll
            for (int s = 0; s < 2; s++) {
                const bf16* Bsx = (s == 0) ? Bs0 : Bs1;
                bF[s][0] = *reinterpret_cast<const uint32_t*>(&Bsx[b0]);
                bF[s][1] = *reinterpret_cast<const uint32_t*>(&Bsx[b0 + 8]);
            }
#pragma unroll
            for (int ma = 0; ma < 2; ma++) {
                float* c = acc[ma][nb];
                mma_bf16(c, aF[0][ma], bF[1]);   // h*m
                mma_bf16(c, aF[1][ma], bF[0]);   // m*h
                mma_bf16(c, aF[0][ma], bF[0]);   // h*h
            }
        }
        __syncthreads();
    }

#pragma unroll
    for (int ma = 0; ma < 2; ma++) {
        int row0 = rowBase + mWarp + ma * 16 + g;
#pragma unroll
        for (int nb = 0; nb < 8; nb++) {
            int col = colBase + nWarp + nb * 8 + 2 * t;
            float2 bv = *reinterpret_cast<const float2*>(&bias[col]);
            float2 v0, v1;
            v0.x = acc[ma][nb][0] + bv.x;
            v0.y = acc[ma][nb][1] + bv.y;
            v1.x = acc[ma][nb][2] + bv.x;
            v1.y = acc[ma][nb][3] + bv.y;
            if (RELU) {
                v0.x = fmaxf(v0.x, 0.f); v0.y = fmaxf(v0.y, 0.f);
                v1.x = fmaxf(v1.x, 0.f); v1.y = fmaxf(v1.y, 0.f);
            }
            *reinterpret_cast<float2*>(&C[(size_t)row0 * N + col]) = v0;
            *reinterpret_cast<float2*>(&C[(size_t)(row0 + 8) * N + col]) = v1;
        }
    }
}

// ---------------- fused residual quantization -> packed indices ------------
__global__ __launch_bounds__(256) void quant_all(
    const float* __restrict__ z, const float* __restrict__ codebooks,
    uint32_t* __restrict__ idxOut, float* __restrict__ partials)
{
    __shared__ __align__(16) float sC[64 * D3];
    __shared__ float snorm[64];
    __shared__ float sred[256];

    const int tid = threadIdx.x;
    const size_t row = (size_t)blockIdx.x * 256 + tid;

    ull r2[64];
    {
        const ulonglong2* zp = reinterpret_cast<const ulonglong2*>(z + row * D3);
#pragma unroll
        for (int k = 0; k < 32; k++) {
            ulonglong2 v = zp[k];
            r2[2 * k] = v.x; r2[2 * k + 1] = v.y;
        }
    }
    ull mone; PACK2(mone, -1.0f, -1.0f);
    ull ls0 = 0ULL, ls1 = 0ULL;
    uint32_t packed = 0;

    for (int l = 0; l < NLEVELS; l++) {
        const float* C = codebooks + (size_t)l * NCODES * D3;
        float best = 3.4e38f;
        int bi = 0;

        for (int ch = 0; ch < 4; ch++) {
            __syncthreads();
            const float4* src =
                reinterpret_cast<const float4*>(C + (size_t)ch * 64 * D3);
            float4* dst = reinterpret_cast<float4*>(sC);
#pragma unroll
            for (int i = 0; i < 8; i++) dst[tid + i * 256] = src[tid + i * 256];
            __syncthreads();
            if (tid < 64) {
                const float4* cp = reinterpret_cast<const float4*>(sC + tid * D3);
                float s = 0.0f;
#pragma unroll
                for (int i = 0; i < 32; i++) {
                    float4 v = cp[i];
                    s += v.x * v.x + v.y * v.y + v.z * v.z + v.w * v.w;
                }
                snorm[tid] = s;
            }
            __syncthreads();

            for (int c = 0; c < 64; c++) {
                const ulonglong2* cp =
                    reinterpret_cast<const ulonglong2*>(sC + c * D3);
                ull a0 = 0ULL, a1 = 0ULL;
#pragma unroll
                for (int k = 0; k < 32; k++) {
                    ulonglong2 v = cp[k];
                    FMA2(a0, r2[2 * k],     v.x);
                    FMA2(a1, r2[2 * k + 1], v.y);
                }
                float s0, s1, s2, s3;
                UNPACK2(s0, s1, a0);
                UNPACK2(s2, s3, a1);
                float dot = (s0 + s1) + (s2 + s3);
                float score = snorm[c] - 2.0f * dot;
                if (score < best) { best = score; bi = ch * 64 + c; }
            }
        }

        packed |= (uint32_t)bi << (8 * l);

        const ulonglong2* qp =
            reinterpret_cast<const ulonglong2*>(C + (size_t)bi * D3);
#pragma unroll
        for (int k = 0; k < 32; k++) {
            ulonglong2 q = qp[k];
            ull d0, d1;
            FMA2D(d0, q.x, mone, r2[2 * k]);      // r - q
            FMA2D(d1, q.y, mone, r2[2 * k + 1]);
            FMA2(ls0, d0, d0);
            FMA2(ls1, d1, d1);
            r2[2 * k] = d0; r2[2 * k + 1] = d1;
        }
    }

    idxOut[row] = packed;

    float s0, s1, s2, s3;
    UNPACK2(s0, s1, ls0);
    UNPACK2(s2, s3, ls1);
    sred[tid] = (s0 + s1) + (s2 + s3);
    __syncthreads();
#pragma unroll
    for (int s = 128; s > 0; s >>= 1) {
        if (tid < s) sred[tid] += sred[tid + s];
        __syncthreads();
    }
    if (tid == 0) partials[blockIdx.x] = sred[0];
}

// ---------------- dec1 via lookup: h2 = relu(Σ_l P[l][idx_l] + db0) --------
__global__ __launch_bounds__(256) void dec1_lookup(
    const uint32_t* __restrict__ idx, const float* __restrict__ P,
    const float* __restrict__ bias, float* __restrict__ h2)
{
    const int tid = threadIdx.x;
    const int row = blockIdx.x * 32 + (tid >> 3);
    const int c0  = (tid & 7) * 32;

    uint32_t iw = idx[row];
    float4 acc[8];
    const float4* bp = reinterpret_cast<const float4*>(bias + c0);
#pragma unroll
    for (int j = 0; j < 8; j++) acc[j] = bp[j];

#pragma unroll
    for (int l = 0; l < NLEVELS; l++) {
        int code = (iw >> (8 * l)) & 255;
        const float4* pp = reinterpret_cast<const float4*>(
            P + ((size_t)(l * NCODES + code) * D2) + c0);
#pragma unroll
        for (int j = 0; j < 8; j++) {
            float4 v = pp[j];
            acc[j].x += v.x; acc[j].y += v.y;
            acc[j].z += v.z; acc[j].w += v.w;
        }
    }

    float4* op = reinterpret_cast<float4*>(h2 + (size_t)row * D2 + c0);
#pragma unroll
    for (int j = 0; j < 8; j++) {
        float4 o = acc[j];
        o.x = fmaxf(o.x, 0.f); o.y = fmaxf(o.y, 0.f);
        o.z = fmaxf(o.z, 0.f); o.w = fmaxf(o.w, 0.f);
        op[j] = o;
    }
}

// ---------------- deterministic loss finalize ----------------
__global__ void finalize_loss(const float* __restrict__ partials,
                              float* __restrict__ out)
{
    if (threadIdx.x == 0 && blockIdx.x == 0) {
        float tot = 0.0f;
        for (int i = 0; i < QBLOCKS; i++) tot += partials[i];
        float rq = (1.0f + BETA_F) * tot /
                   ((float)NLEVELS * (float)BATCH * (float)D3);
        *out = rq;
    }
}

// ---------------- launch ----------------
extern "C" void kernel_launch(void* const* d_in, const int* in_sizes, int n_in,
                              void* d_out, int out_size)
{
    (void)in_sizes; (void)n_in;
    const float* x   = (const float*)d_in[0];
    const float* ew0 = (const float*)d_in[1];
    const float* eb0 = (const float*)d_in[2];
    const float* ew1 = (const float*)d_in[3];
    const float* eb1 = (const float*)d_in[4];
    const float* ew2 = (const float*)d_in[5];
    const float* eb2 = (const float*)d_in[6];
    const float* dw0 = (const float*)d_in[7];
    const float* db0 = (const float*)d_in[8];
    const float* dw1 = (const float*)d_in[9];
    const float* db1 = (const float*)d_in[10];
    const float* dw2 = (const float*)d_in[11];
    const float* db2 = (const float*)d_in[12];
    const float* cb  = (const float*)d_in[13];
    float* out = (float*)d_out;

    float *h1, *h2, *z, *P, *zb, *lp;
    uint32_t* idx;
    bf16 *w0, *w1;
    cudaGetSymbolAddress((void**)&h1,  g_h1);
    cudaGetSymbolAddress((void**)&h2,  g_h2);
    cudaGetSymbolAddress((void**)&z,   g_z);
    cudaGetSymbolAddress((void**)&idx, g_idx);
    cudaGetSymbolAddress((void**)&P,   g_P);
    cudaGetSymbolAddress((void**)&zb,  g_zb);
    cudaGetSymbolAddress((void**)&lp,  g_loss_part);
    cudaGetSymbolAddress((void**)&w0,  g_wb0);
    cudaGetSymbolAddress((void**)&w1,  g_wb1);

    // decoder weight splits for dw1, dw2 only (transposed to [N][K])
    // dw1: 256x512 -> offset 0 ; dw2: 512x768 -> offset 131072
    wsplit<<<(D2 * D1 + 255) / 256, 256>>>(dw1, w0,          w1,          D2, D1);
    wsplit<<<(D1 * D0 + 255) / 256, 256>>>(dw2, w0 + 131072, w1 + 131072, D1, D0);

    const int MB = BATCH / 128;

    // P = codebooks @ dw0  (M=1024, N=256, K=128)
    sgemm_bias<false><<<dim3(D2 / 64, (NLEVELS * NCODES) / 128), 256>>>(
        cb, dw0, zb, P, NLEVELS * NCODES, D2, D3);

    // encoder: scalar (flip-safe)
    sgemm_bias<true ><<<dim3(D1 / 64, MB), 256>>>(x,  ew0, eb0, h1, BATCH, D1, D0);
    sgemm_bias<true ><<<dim3(D2 / 64, MB), 256>>>(h1, ew1, eb1, h2, BATCH, D2, D1);
    sgemm_bias<false><<<dim3(D3 / 64, MB), 256>>>(h2, ew2, eb2, z,  BATCH, D3, D2);

    // fused residual quantization -> indices + loss partials
    quant_all<<<QBLOCKS, 256>>>(z, cb, idx, lp);

    // dec1 via table lookup
    dec1_lookup<<<BATCH / 32, 256>>>(idx, P, db0, h2);

    // dec2, dec3: bf16x2 mma (R6 proven decoder)
    mma_gemm<true ><<<dim3(D1 / 128, MB), 256>>>(h2, w0,          w1,          db1, h1,  BATCH, D1, D2);
    mma_gemm<false><<<dim3(D0 / 128, MB), 256>>>(h1, w0 + 131072, w1 + 131072, db2, out, BATCH, D0, D1);

    finalize_loss<<<1, 32>>>(lp, out + (size_t)out_size - 1);
}